// round 3
// baseline (speedup 1.0000x reference)
#include <cuda_runtime.h>
#include <math.h>

// DGPLoss fused single-kernel, band-strip layout:
//   seg_feat: [4, 64, 512, 512] fp32   (d_in[0])
//   dep_true: [4, 1, 512, 512]  fp32   (d_in[1])
//   out[0]  : scalar fp32
//
// One thread = 4-wide x 5-tall strip within one 5-row patch band, so the two
// center scalars per channel are loaded ONCE and reused across all 5 rows
// (5x fewer center LDGs than pixel-per-thread layout). 20 accumulators/thread.
// Block = 128 threads (covers a full 512-wide band), grid = (102 bands, 4 batch).
// Last block (ticket) does the deterministic final reduction over 408 partials.

#define EPSF 1e-8f
#define EPS2 1e-16f
#define CS   262144              // 512*512
#define NBANDS 102
#define NBAT 4
#define NPART (NBANDS * NBAT)    // 408

__device__ float2       g_part[NPART];
__device__ unsigned int g_ticket;   // zero-init; reset by last block each run

__global__ __launch_bounds__(128, 8)
void dgp_fused(const float* __restrict__ seg, const float* __restrict__ dep,
               float* __restrict__ out)
{
    const int tid = threadIdx.x;
    const int j   = blockIdx.x;         // patch band 0..101 (rows 5j..5j+4)
    const int b   = blockIdx.y;         // batch 0..3
    const int h0  = j * 5;
    const int hc  = h0 + 2;
    const int w0  = tid << 2;           // 0,4,...,508

    const int pA  = w0 / 5;
    const int pB  = (w0 + 3) / 5;
    const int wcA = pA * 5 + 2;
    const int wcB = pB * 5 + 2;
    const bool sB1 = ((w0 + 1) / 5) != pA;
    const bool sB2 = ((w0 + 2) / 5) != pA;
    const bool sB3 = (pB != pA);

    const int segBase = b * (64 * CS);  // max ~50.3M elements, fits int32
    const float* __restrict__ pix0 = seg + segBase + h0 * 512 + w0;
    const float* __restrict__ ctA  = seg + segBase + hc * 512 + wcA;
    const float* __restrict__ ctB  = seg + segBase + hc * 512 + wcB;

    float acc[5][4];
    #pragma unroll
    for (int r = 0; r < 5; ++r)
        #pragma unroll
        for (int k = 0; k < 4; ++k) acc[r][k] = 0.f;

    for (int c = 0; c < 64; ++c) {
        const float qA = ctA[c * CS];
        const float qB = ctB[c * CS];
        const float q1 = sB1 ? qB : qA;
        const float q2 = sB2 ? qB : qA;
        const float q3 = sB3 ? qB : qA;
        const float* __restrict__ rowp = pix0 + c * CS;
        #pragma unroll
        for (int r = 0; r < 5; ++r) {
            const float4 p = *(const float4*)(rowp + r * 512);
            float d;
            d = qA - p.x; acc[r][0] = fmaf(d, d, acc[r][0]);
            d = q1 - p.y; acc[r][1] = fmaf(d, d, acc[r][1]);
            d = q2 - p.z; acc[r][2] = fmaf(d, d, acc[r][2]);
            d = q3 - p.w; acc[r][3] = fmaf(d, d, acc[r][3]);
        }
    }

    // --- depth branch + mask + per-thread partial ---
    const int depBase = b * CS;
    const float dcA = dep[depBase + hc * 512 + wcA];
    const float dcB = dep[depBase + hc * 512 + wcB];
    float dc[4];
    dc[0] = dcA;
    dc[1] = sB1 ? dcB : dcA;
    dc[2] = sB2 ? dcB : dcA;
    dc[3] = sB3 ? dcB : dcA;
    int wcv[4];
    wcv[0] = wcA;
    wcv[1] = sB1 ? wcB : wcA;
    wcv[2] = sB2 ? wcB : wcA;
    wcv[3] = sB3 ? wcB : wcA;

    float sum = 0.f, cnt = 0.f;
    #pragma unroll
    for (int r = 0; r < 5; ++r) {
        const float4 dq = *(const float4*)(dep + depBase + (h0 + r) * 512 + w0);
        float dpv[4] = {dq.x, dq.y, dq.z, dq.w};
        #pragma unroll
        for (int k = 0; k < 4; ++k) {
            const float dd = fabsf(dc[k] - dpv[k]);
            const bool ic  = (r == 2) && (w0 + k == wcv[k]);
            const bool m   = (dd > EPSF) && (acc[r][k] > EPS2) &&
                             (dpv[k] > EPSF) && !ic && (w0 + k < 510);
            if (m) {
                sum += __expf(-fmaf(dd, 0.1f, acc[r][k]));
                cnt += 1.f;
            }
        }
    }

    // --- intra-block reduce ---
    #pragma unroll
    for (int o = 16; o > 0; o >>= 1) {
        sum += __shfl_down_sync(0xFFFFFFFFu, sum, o);
        cnt += __shfl_down_sync(0xFFFFFFFFu, cnt, o);
    }

    __shared__ float2 sw[4];
    __shared__ bool   isLast;
    const int lane = tid & 31;
    const int wid  = tid >> 5;
    if (lane == 0) sw[wid] = make_float2(sum, cnt);
    __syncthreads();

    if (tid == 0) {
        const float2 t0 = sw[0], t1 = sw[1], t2 = sw[2], t3 = sw[3];
        g_part[blockIdx.x + NBANDS * blockIdx.y] =
            make_float2(t0.x + t1.x + t2.x + t3.x, t0.y + t1.y + t2.y + t3.y);
        __threadfence();
        const unsigned t = atomicAdd(&g_ticket, 1u);
        isLast = (t == NPART - 1);
    }
    __syncthreads();

    // --- final deterministic reduction by the last block ---
    if (isLast) {
        __threadfence();
        float s = 0.f, c = 0.f;
        #pragma unroll 4
        for (int i = tid; i < NPART; i += 128) {
            const float2 v = g_part[i];
            s += v.x; c += v.y;
        }
        #pragma unroll
        for (int o = 16; o > 0; o >>= 1) {
            s += __shfl_down_sync(0xFFFFFFFFu, s, o);
            c += __shfl_down_sync(0xFFFFFFFFu, c, o);
        }
        if (lane == 0) sw[wid] = make_float2(s, c);
        __syncthreads();
        if (tid == 0) {
            const float2 t0 = sw[0], t1 = sw[1], t2 = sw[2], t3 = sw[3];
            const float ts = t0.x + t1.x + t2.x + t3.x;
            const float tc = t0.y + t1.y + t2.y + t3.y;
            out[0] = ts / fmaxf(tc, 1.0f);
            g_ticket = 0u;   // reset for next graph replay
        }
    }
}

extern "C" void kernel_launch(void* const* d_in, const int* in_sizes, int n_in,
                              void* d_out, int out_size) {
    const float* seg = (const float*)d_in[0];   // [4,64,512,512]
    const float* dep = (const float*)d_in[1];   // [4,1,512,512]
    float* out = (float*)d_out;

    dim3 grid(NBANDS, NBAT);
    dgp_fused<<<grid, 128>>>(seg, dep, out);
}